// round 16
// baseline (speedup 1.0000x reference)
#include <cuda_runtime.h>
#include <cuda_fp16.h>
#include <cstdint>

#define MOD_SCALE  0.04419417382415922f     // 1/sqrt(512)
#define CONV_SCALE 0.014731391274719738f    // 1/sqrt(512*9)

// ------------------------- device scratch (no allocs) ----------------------
__device__ float g_s [8*512];
__device__ float g_w2[512*512];
__device__ float g_dm[8*512];
__device__ __align__(16) __half g_wf[9*512*512];            // [tap][oc][ic]
__device__ __align__(16) __half g_xf[(size_t)8*66*66*512];  // [b][r][c][ic]

// ------------------------- helpers -----------------------------------------
static __device__ __forceinline__ uint32_t smem_u32(const void* p) {
    uint32_t a;
    asm("{ .reg .u64 t; cvta.to.shared.u64 t, %1; cvt.u32.u64 %0, t; }"
        : "=r"(a) : "l"(p));
    return a;
}
#define CP16(dst, src) \
    asm volatile("cp.async.cg.shared.global [%0], [%1], 16;" :: "r"(dst), "l"(src))
#define CP_COMMIT() asm volatile("cp.async.commit_group;" ::: "memory")
#define CP_WAIT(n)  asm volatile("cp.async.wait_group %0;" :: "n"(n) : "memory")

#define SWZ(o) ((o) ^ (((o) >> 3) & 0x70))

static __device__ __forceinline__ void ldsm4(uint32_t* r, uint32_t addr) {
    asm volatile("ldmatrix.sync.aligned.m8n8.x4.shared.b16 {%0,%1,%2,%3}, [%4];"
                 : "=r"(r[0]), "=r"(r[1]), "=r"(r[2]), "=r"(r[3]) : "r"(addr));
}
static __device__ __forceinline__ void mma16816(float* c, const uint32_t* a,
                                                const uint32_t* b) {
    asm volatile(
        "mma.sync.aligned.m16n8k16.row.col.f32.f16.f16.f32 "
        "{%0,%1,%2,%3}, {%4,%5,%6,%7}, {%8,%9}, {%0,%1,%2,%3};"
        : "+f"(c[0]), "+f"(c[1]), "+f"(c[2]), "+f"(c[3])
        : "r"(a[0]), "r"(a[1]), "r"(a[2]), "r"(a[3]), "r"(b[0]), "r"(b[1]));
}

// ------------------------- prep kernels ------------------------------------
static __device__ __forceinline__ float warp_sum(float p) {
#pragma unroll
    for (int o = 16; o; o >>= 1) p += __shfl_xor_sync(0xffffffffu, p, o);
    return p;
}

__global__ void k_style(const float* __restrict__ style, const float* __restrict__ mw,
                        const float* __restrict__ mb) {
    int W = blockIdx.x * 8 + (threadIdx.x >> 5), lane = threadIdx.x & 31;
    int b = W >> 9, i = W & 511;
    const float* st = style + b * 512;
    const float* mr = mw + (size_t)i * 512;
    float p = 0.f;
#pragma unroll 4
    for (int d = lane; d < 512; d += 32) p += st[d] * mr[d];
    p = warp_sum(p);
    if (lane == 0) g_s[b * 512 + i] = p * MOD_SCALE + mb[i];
}

// fused: fp16 tap-major weights + per-(o,i) squared norms
__global__ void k_wprep(const float* __restrict__ w) {
    int idx = blockIdx.x * blockDim.x + threadIdx.x;   // o*512 + i
    const float* p = w + (size_t)idx * 9;
    float acc = 0.f;
#pragma unroll
    for (int t = 0; t < 9; t++) {
        float v = p[t];
        acc += v * v;
        g_wf[(size_t)t * 262144 + idx] = __float2half_rn(v);
    }
    g_w2[idx] = acc;
}

__global__ void k_demod() {
    int W = blockIdx.x * 8 + (threadIdx.x >> 5), lane = threadIdx.x & 31;
    int b = W >> 9, o = W & 511;
    float p = 0.f;
#pragma unroll 4
    for (int i = lane; i < 512; i += 32) {
        float sv = g_s[b * 512 + i];
        p += g_w2[o * 512 + i] * sv * sv;
    }
    p = warp_sum(p);
    if (lane == 0)
        g_dm[b * 512 + o] = CONV_SCALE * rsqrtf(CONV_SCALE * CONV_SCALE * p + 1e-8f);
}

// padded+transposed+scaled fp16 input: g_xf[b][r][c][ic], r,c in [0,66)
__global__ void k_xconv(const float* __restrict__ x) {
    __shared__ float t[64][65];
    int r = blockIdx.x + 1, icc = blockIdx.y, b = blockIdx.z;
    int tx = threadIdx.x, ty = threadIdx.y;
    const float* xp = x + (((size_t)(b * 512 + icc * 64)) << 12) + ((r - 1) << 6);
#pragma unroll
    for (int k = 0; k < 8; k++) {
        int icl = ty + k * 8;
        float2 v = *(const float2*)(xp + ((size_t)icl << 12) + tx * 2);
        t[icl][tx * 2] = v.x; t[icl][tx * 2 + 1] = v.y;
    }
    __syncthreads();
    int ic = icc * 64 + 2 * tx;
    float s0 = g_s[b * 512 + ic], s1 = g_s[b * 512 + ic + 1];
#pragma unroll
    for (int k = 0; k < 8; k++) {
        int c = ty + k * 8;
        size_t o = ((size_t)(b * 66 + r) * 66 + (c + 1)) * 512 + ic;
        *(__half2*)(g_xf + o) =
            __floats2half2_rn(t[2 * tx][c] * s0, t[2 * tx + 1][c] * s1);
    }
}

__global__ void k_xborder() {                 // zero the pad ring
    int i = blockIdx.x % 260, b = blockIdx.x / 260;
    int r, c;
    if      (i < 66)  { r = 0;        c = i;        }
    else if (i < 132) { r = 65;       c = i - 66;   }
    else if (i < 196) { r = i - 131;  c = 0;        }
    else              { r = i - 195;  c = 65;       }
    size_t o = ((size_t)(b * 66 + r) * 66 + c) * 512 + threadIdx.x * 2;
    *(__half2*)(g_xf + o) = __floats2half2_rn(0.f, 0.f);
}

// ------------------------- main mma.sync conv -------------------------------
// Grid 1160. blockIdx < 888: FULL tile (128oc x 128px) = units 0..887
// (exactly 3 waves of 296). blockIdx >= 888: HALF tile (128oc x 64px),
// two per remaining unit (units 888..1023), dispatched last => they fill the
// tail wave at ~d/2 each: makespan ~3.55d instead of 4d. Per-element math is
// identical (split over pixels, not K) => bitwise-same output.
__global__ void __launch_bounds__(256, 2) k_mma(float* __restrict__ out) {
    extern __shared__ char dynsm[];

    const int tid = threadIdx.x, wid = tid >> 5, lane = tid & 31;
    const uint32_t sb  = (smem_u32(dynsm) + 1023u) & ~1023u;
    const uint32_t sB0 = sb + 32768;              // halo buffers after 2 A slots

    // per-thread ldmatrix address components
    const int la15 = lane & 15;
    const int aK   = lane & 16;
    const int bRow = (lane & 7) + ((lane & 16) >> 1);
    const int bK   = (lane & 8) << 1;

    if (blockIdx.x < 888) {
        // ================= FULL tile (proven R13/R15 core) ==================
        const int u = blockIdx.x;
        const int combo = u & 31, chunk = u >> 5;
        const int b = combo >> 2, ocb = (combo & 3) << 7;
        const int n0 = chunk << 7, R0 = chunk << 1;

        const int m_base = (wid & 1) << 6;
        const int n_base = (wid >> 1) << 5;

        float acc[4][4][4];
#pragma unroll
        for (int mt = 0; mt < 4; mt++)
#pragma unroll
            for (int nt = 0; nt < 4; nt++)
#pragma unroll
                for (int q = 0; q < 4; q++) acc[mt][nt][q] = 0.f;

        auto fill_A = [&](int s) {
            const int kc = s / 9, tap = s - kc * 9, ic0 = kc << 6;
            const uint32_t base = sb + ((s & 1) << 14);
#pragma unroll
            for (int it = 0; it < 4; it++) {
                const int id = tid + (it << 8);
                const int row = id >> 3, j = id & 7;
                CP16(base + SWZ((row << 7) + (j << 4)),
                     (const char*)(g_wf + (((size_t)(tap * 512 + ocb + row) << 9) + ic0))
                     + (j << 4));
            }
            CP_COMMIT();
        };
        auto fill_B = [&](int kc) {
            const int ic0 = kc << 6;
            const uint32_t base = sB0 + (uint32_t)(kc & 1) * 33792u;
#pragma unroll
            for (int it = 0; it < 9; it++) {
                const int id = tid + (it << 8);
                if (id < 2112) {
                    const int hr = id >> 3, j = id & 7;
                    const int pr4 = hr / 66, c = hr - pr4 * 66;
                    CP16(base + SWZ((hr << 7) + (j << 4)),
                         (const char*)(g_xf +
                             (((size_t)((b * 66 + R0 + pr4) * 66 + c) << 9) + ic0))
                         + (j << 4));
                }
            }
            CP_COMMIT();
        };

        fill_B(0); fill_A(0);

#pragma unroll 1
        for (int s = 0; s < 72; s++) {
            const int kc = s / 9, tap = s - kc * 9;
            const int dy = tap / 3, dx = tap - dy * 3;

            if (tap == 0 && kc + 1 < 8) fill_B(kc + 1); else CP_COMMIT();
            if (s + 1 < 72)             fill_A(s + 1);  else CP_COMMIT();

            CP_WAIT(2);
            __syncthreads();

            const uint32_t sA  = sb + ((s & 1) << 14);
            const uint32_t sBb = sB0 + (uint32_t)(kc & 1) * 33792u;

            int hRow[2];
#pragma unroll
            for (int h = 0; h < 2; h++) {
                const int pix = n_base + (h << 4) + bRow;
                hRow[h] = ((pix >> 6) + dy) * 66 + (pix & 63) + dx;
            }

#pragma unroll
            for (int ks = 0; ks < 4; ks++) {
                const int kb = ks << 5;
                uint32_t ah[4][4], bh[2][4];
#pragma unroll
                for (int mt = 0; mt < 4; mt++)
                    ldsm4(ah[mt], sA + SWZ(((m_base + (mt << 4) + la15) << 7) + kb + aK));
#pragma unroll
                for (int h = 0; h < 2; h++)
                    ldsm4(bh[h], sBb + SWZ((hRow[h] << 7) + kb + bK));
#pragma unroll
                for (int mt = 0; mt < 4; mt++)
#pragma unroll
                    for (int nt = 0; nt < 4; nt++)
                        mma16816(acc[mt][nt], ah[mt], &bh[nt >> 1][(nt & 1) << 1]);
            }
            __syncthreads();
        }

        const int oc0  = ocb + m_base + (lane >> 2);
        const int pixb = n0 + n_base + ((lane & 3) << 1);
#pragma unroll
        for (int mt = 0; mt < 4; mt++) {
            const int ocr = oc0 + (mt << 4);
            const float dm0 = g_dm[b * 512 + ocr];
            const float dm1 = g_dm[b * 512 + ocr + 8];
            float* p0 = out + (((size_t)(b * 512 + ocr)) << 12);
            float* p1 = p0 + (8 << 12);
#pragma unroll
            for (int nt = 0; nt < 4; nt++) {
                const int px = pixb + (nt << 3);
                *(float2*)(p0 + px) = make_float2(acc[mt][nt][0] * dm0,
                                                  acc[mt][nt][1] * dm0);
                *(float2*)(p1 + px) = make_float2(acc[mt][nt][2] * dm1,
                                                  acc[mt][nt][3] * dm1);
            }
        }
    } else {
        // ================= HALF tile: 128 oc x 64 px =======================
        const int h2 = blockIdx.x - 888;
        const int u = 888 + (h2 >> 1), half = h2 & 1;
        const int combo = u & 31, chunk = u >> 5;
        const int b = combo >> 2, ocb = (combo & 3) << 7;
        const int n0 = (chunk << 7) + (half << 6);
        const int R0 = (chunk << 1) + half;       // padded halo base row

        const int m_base = (wid & 3) << 5;        // 4 m-groups of 32 oc
        const int n_base = (wid >> 2) << 5;       // 2 n-groups of 32 px

        float acc[2][4][4];
#pragma unroll
        for (int mt = 0; mt < 2; mt++)
#pragma unroll
            for (int nt = 0; nt < 4; nt++)
#pragma unroll
                for (int q = 0; q < 4; q++) acc[mt][nt][q] = 0.f;

        auto fill_A = [&](int s) {
            const int kc = s / 9, tap = s - kc * 9, ic0 = kc << 6;
            const uint32_t base = sb + ((s & 1) << 14);
#pragma unroll
            for (int it = 0; it < 4; it++) {
                const int id = tid + (it << 8);
                const int row = id >> 3, j = id & 7;
                CP16(base + SWZ((row << 7) + (j << 4)),
                     (const char*)(g_wf + (((size_t)(tap * 512 + ocb + row) << 9) + ic0))
                     + (j << 4));
            }
            CP_COMMIT();
        };
        // halo: 3 padded rows x 66 cols = 198 rows -> 1584 CP16
        auto fill_B = [&](int kc) {
            const int ic0 = kc << 6;
            const uint32_t base = sB0 + (uint32_t)(kc & 1) * 33792u;
#pragma unroll
            for (int it = 0; it < 7; it++) {
                const int id = tid + (it << 8);
                if (id < 1584) {
                    const int hr = id >> 3, j = id & 7;
                    const int pr3 = hr / 66, c = hr - pr3 * 66;
                    CP16(base + SWZ((hr << 7) + (j << 4)),
                         (const char*)(g_xf +
                             (((size_t)((b * 66 + R0 + pr3) * 66 + c) << 9) + ic0))
                         + (j << 4));
                }
            }
            CP_COMMIT();
        };

        fill_B(0); fill_A(0);

#pragma unroll 1
        for (int s = 0; s < 72; s++) {
            const int kc = s / 9, tap = s - kc * 9;
            const int dy = tap / 3, dx = tap - dy * 3;

            if (tap == 0 && kc + 1 < 8) fill_B(kc + 1); else CP_COMMIT();
            if (s + 1 < 72)             fill_A(s + 1);  else CP_COMMIT();

            CP_WAIT(2);
            __syncthreads();

            const uint32_t sA  = sb + ((s & 1) << 14);
            const uint32_t sBb = sB0 + (uint32_t)(kc & 1) * 33792u;

            int hRow[2];
#pragma unroll
            for (int h = 0; h < 2; h++) {
                const int pix = n_base + (h << 4) + bRow;   // < 64
                hRow[h] = dy * 66 + pix + dx;
            }

#pragma unroll
            for (int ks = 0; ks < 4; ks++) {
                const int kb = ks << 5;
                uint32_t ah[2][4], bh[2][4];
#pragma unroll
                for (int mt = 0; mt < 2; mt++)
                    ldsm4(ah[mt], sA + SWZ(((m_base + (mt << 4) + la15) << 7) + kb + aK));
#pragma unroll
                for (int h = 0; h < 2; h++)
                    ldsm4(bh[h], sBb + SWZ((hRow[h] << 7) + kb + bK));
#pragma unroll
                for (int mt = 0; mt < 2; mt++)
#pragma unroll
                    for (int nt = 0; nt < 4; nt++)
                        mma16816(acc[mt][nt], ah[mt], &bh[nt >> 1][(nt & 1) << 1]);
            }
            __syncthreads();
        }

        const int oc0  = ocb + m_base + (lane >> 2);
        const int pixb = n0 + n_base + ((lane & 3) << 1);
#pragma unroll
        for (int mt = 0; mt < 2; mt++) {
            const int ocr = oc0 + (mt << 4);
            const float dm0 = g_dm[b * 512 + ocr];
            const float dm1 = g_dm[b * 512 + ocr + 8];
            float* p0 = out + (((size_t)(b * 512 + ocr)) << 12);
            float* p1 = p0 + (8 << 12);
#pragma unroll
            for (int nt = 0; nt < 4; nt++) {
                const int px = pixb + (nt << 3);
                *(float2*)(p0 + px) = make_float2(acc[mt][nt][0] * dm0,
                                                  acc[mt][nt][1] * dm0);
                *(float2*)(p1 + px) = make_float2(acc[mt][nt][2] * dm1,
                                                  acc[mt][nt][3] * dm1);
            }
        }
    }
}

// ------------------------- launch ------------------------------------------
extern "C" void kernel_launch(void* const* d_in, const int* in_sizes, int n_in,
                              void* d_out, int out_size) {
    const float* input  = (const float*)d_in[0];   // [8,512,64,64]
    const float* style  = (const float*)d_in[1];   // [8,512]
    const float* weight = (const float*)d_in[2];   // [1,512,512,3,3]
    const float* mod_w  = (const float*)d_in[3];   // [512,512]
    const float* mod_b  = (const float*)d_in[4];   // [512]
    float* out = (float*)d_out;                    // [8,512,64,64]

    // 2 A slots (32KB) + 2 B halo buffers (2x33792) + 1KB align pad
    const int SMEM_DYN = 32768 + 2 * 33792 + 1024;
    cudaFuncSetAttribute(k_mma, cudaFuncAttributeMaxDynamicSharedMemorySize, SMEM_DYN);

    k_style  <<<512, 256>>>(style, mod_w, mod_b);
    k_wprep  <<<1024, 256>>>(weight);
    k_demod  <<<512, 256>>>();
    k_xconv  <<<dim3(64, 8, 8), dim3(32, 8)>>>(input);
    k_xborder<<<2080, 256>>>();
    k_mma    <<<1160, 256, SMEM_DYN>>>(out);       // 888 fulls + 272 halves
}

// round 17
// speedup vs baseline: 1.1083x; 1.1083x over previous
#include <cuda_runtime.h>
#include <cuda_fp16.h>
#include <cstdint>

#define MOD_SCALE  0.04419417382415922f     // 1/sqrt(512)
#define CONV_SCALE 0.014731391274719738f    // 1/sqrt(512*9)

// ------------------------- device scratch (no allocs) ----------------------
__device__ float g_s [8*512];
__device__ float g_w2[512*512];
__device__ float g_dm[8*512];
__device__ __align__(16) __half g_wf[9*512*512];            // [tap][oc][ic]
__device__ __align__(16) __half g_xf[(size_t)8*66*66*512];  // [b][r][c][ic]

// ------------------------- helpers -----------------------------------------
static __device__ __forceinline__ uint32_t smem_u32(const void* p) {
    uint32_t a;
    asm("{ .reg .u64 t; cvta.to.shared.u64 t, %1; cvt.u32.u64 %0, t; }"
        : "=r"(a) : "l"(p));
    return a;
}
#define CP16(dst, src) \
    asm volatile("cp.async.cg.shared.global [%0], [%1], 16;" :: "r"(dst), "l"(src))
#define CP_COMMIT() asm volatile("cp.async.commit_group;" ::: "memory")
#define CP_WAIT(n)  asm volatile("cp.async.wait_group %0;" :: "n"(n) : "memory")

#define SWZ(o) ((o) ^ (((o) >> 3) & 0x70))

static __device__ __forceinline__ void ldsm4(uint32_t* r, uint32_t addr) {
    asm volatile("ldmatrix.sync.aligned.m8n8.x4.shared.b16 {%0,%1,%2,%3}, [%4];"
                 : "=r"(r[0]), "=r"(r[1]), "=r"(r[2]), "=r"(r[3]) : "r"(addr));
}
static __device__ __forceinline__ void mma16816(float* c, const uint32_t* a,
                                                const uint32_t* b) {
    asm volatile(
        "mma.sync.aligned.m16n8k16.row.col.f32.f16.f16.f32 "
        "{%0,%1,%2,%3}, {%4,%5,%6,%7}, {%8,%9}, {%0,%1,%2,%3};"
        : "+f"(c[0]), "+f"(c[1]), "+f"(c[2]), "+f"(c[3])
        : "r"(a[0]), "r"(a[1]), "r"(a[2]), "r"(a[3]), "r"(b[0]), "r"(b[1]));
}

// ------------------------- prep kernels ------------------------------------
static __device__ __forceinline__ float warp_sum(float p) {
#pragma unroll
    for (int o = 16; o; o >>= 1) p += __shfl_xor_sync(0xffffffffu, p, o);
    return p;
}

__global__ void k_style(const float* __restrict__ style, const float* __restrict__ mw,
                        const float* __restrict__ mb) {
    int W = blockIdx.x * 8 + (threadIdx.x >> 5), lane = threadIdx.x & 31;
    int b = W >> 9, i = W & 511;
    const float* st = style + b * 512;
    const float* mr = mw + (size_t)i * 512;
    float p = 0.f;
#pragma unroll 4
    for (int d = lane; d < 512; d += 32) p += st[d] * mr[d];
    p = warp_sum(p);
    if (lane == 0) g_s[b * 512 + i] = p * MOD_SCALE + mb[i];
}

// fused: fp16 tap-major weights + per-(o,i) squared norms
__global__ void k_wprep(const float* __restrict__ w) {
    int idx = blockIdx.x * blockDim.x + threadIdx.x;   // o*512 + i
    const float* p = w + (size_t)idx * 9;
    float acc = 0.f;
#pragma unroll
    for (int t = 0; t < 9; t++) {
        float v = p[t];
        acc += v * v;
        g_wf[(size_t)t * 262144 + idx] = __float2half_rn(v);
    }
    g_w2[idx] = acc;
}

__global__ void k_demod() {
    int W = blockIdx.x * 8 + (threadIdx.x >> 5), lane = threadIdx.x & 31;
    int b = W >> 9, o = W & 511;
    float p = 0.f;
#pragma unroll 4
    for (int i = lane; i < 512; i += 32) {
        float sv = g_s[b * 512 + i];
        p += g_w2[o * 512 + i] * sv * sv;
    }
    p = warp_sum(p);
    if (lane == 0)
        g_dm[b * 512 + o] = CONV_SCALE * rsqrtf(CONV_SCALE * CONV_SCALE * p + 1e-8f);
}

// padded+transposed+scaled fp16 input: g_xf[b][r][c][ic], r,c in [0,66)
__global__ void k_xconv(const float* __restrict__ x) {
    __shared__ float t[64][65];
    int r = blockIdx.x + 1, icc = blockIdx.y, b = blockIdx.z;
    int tx = threadIdx.x, ty = threadIdx.y;
    const float* xp = x + (((size_t)(b * 512 + icc * 64)) << 12) + ((r - 1) << 6);
#pragma unroll
    for (int k = 0; k < 8; k++) {
        int icl = ty + k * 8;
        float2 v = *(const float2*)(xp + ((size_t)icl << 12) + tx * 2);
        t[icl][tx * 2] = v.x; t[icl][tx * 2 + 1] = v.y;
    }
    __syncthreads();
    int ic = icc * 64 + 2 * tx;
    float s0 = g_s[b * 512 + ic], s1 = g_s[b * 512 + ic + 1];
#pragma unroll
    for (int k = 0; k < 8; k++) {
        int c = ty + k * 8;
        size_t o = ((size_t)(b * 66 + r) * 66 + (c + 1)) * 512 + ic;
        *(__half2*)(g_xf + o) =
            __floats2half2_rn(t[2 * tx][c] * s0, t[2 * tx + 1][c] * s1);
    }
}

__global__ void k_xborder() {                 // zero the pad ring
    int i = blockIdx.x % 260, b = blockIdx.x / 260;
    int r, c;
    if      (i < 66)  { r = 0;        c = i;        }
    else if (i < 132) { r = 65;       c = i - 66;   }
    else if (i < 196) { r = i - 131;  c = 0;        }
    else              { r = i - 195;  c = 65;       }
    size_t o = ((size_t)(b * 66 + r) * 66 + c) * 512 + threadIdx.x * 2;
    *(__half2*)(g_xf + o) = __floats2half2_rn(0.f, 0.f);
}

// ------------------------- main mma.sync conv -------------------------------
// R15 proven kernel, unchanged: 896 CTAs, blockIdx<128 are DOUBLE tiles
// (2 px-chunk passes), rest singles; per pass M=128oc x N=128px, 8 warps,
// 64x32 warp tiles, ic-chunk outer / tap inner, 33KB shared B halo,
// double-buffered, 2 commit groups + wait_group 2 + two syncs per stage,
// 2 CTAs/SM.
__global__ void __launch_bounds__(256, 2) k_mma(float* __restrict__ out) {
    extern __shared__ char dynsm[];

    const int tid = threadIdx.x, wid = tid >> 5, lane = tid & 31;

    int combo, chunk0, npass;
    if (blockIdx.x < 128) {                       // doubles: chunks 24..31
        npass = 2; combo = blockIdx.x & 31;
        chunk0 = 24 + ((blockIdx.x >> 5) << 1);
    } else {                                      // singles: chunks 0..23
        npass = 1; const int sid = blockIdx.x - 128;
        combo = sid & 31; chunk0 = sid >> 5;
    }
    const int b   = combo >> 2;
    const int ocb = (combo & 3) << 7;

    const uint32_t sb  = (smem_u32(dynsm) + 1023u) & ~1023u;
    const uint32_t sB0 = sb + 32768;              // halo buffers after 2 A slots

    const int m_base = (wid & 1) << 6;            // 0 / 64
    const int n_base = (wid >> 1) << 5;           // 0..96

    // per-thread ldmatrix address components
    const int la15 = lane & 15;
    const int aK   = lane & 16;                   // A: +16B for k8..15
    const int bRow = (lane & 7) + ((lane & 16) >> 1);
    const int bK   = (lane & 8) << 1;

#pragma unroll 1
    for (int pass = 0; pass < npass; pass++) {
        const int chunk = chunk0 + pass;
        const int n0 = chunk << 7;                // 128-pixel chunk
        const int R0 = chunk << 1;                // first image row

        float acc[4][4][4];
#pragma unroll
        for (int mt = 0; mt < 4; mt++)
#pragma unroll
            for (int nt = 0; nt < 4; nt++)
#pragma unroll
                for (int q = 0; q < 4; q++) acc[mt][nt][q] = 0.f;

        // A tile fill: 1024 CP16 across 256 threads (slot s&1)
        auto fill_A = [&](int s) {
            const int kc = s / 9, tap = s - kc * 9, ic0 = kc << 6;
            const uint32_t base = sb + ((s & 1) << 14);
#pragma unroll
            for (int it = 0; it < 4; it++) {
                const int id = tid + (it << 8);
                const int row = id >> 3, j = id & 7;
                CP16(base + SWZ((row << 7) + (j << 4)),
                     (const char*)(g_wf + (((size_t)(tap * 512 + ocb + row) << 9) + ic0))
                     + (j << 4));
            }
            CP_COMMIT();
        };

        // B halo fill: 264 rows x 8 chunks of 16B = 2112 CP16 (buffer kc&1)
        auto fill_B = [&](int kc) {
            const int ic0 = kc << 6;
            const uint32_t base = sB0 + (uint32_t)(kc & 1) * 33792u;
#pragma unroll
            for (int it = 0; it < 9; it++) {
                const int id = tid + (it << 8);
                if (id < 2112) {
                    const int hr = id >> 3, j = id & 7;
                    const int pr4 = hr / 66, c = hr - pr4 * 66;
                    CP16(base + SWZ((hr << 7) + (j << 4)),
                         (const char*)(g_xf +
                             (((size_t)((b * 66 + R0 + pr4) * 66 + c) << 9) + ic0))
                         + (j << 4));
                }
            }
            CP_COMMIT();
        };

        fill_B(0);          // group 1
        fill_A(0);          // group 2

#pragma unroll 1
        for (int s = 0; s < 72; s++) {
            const int kc = s / 9, tap = s - kc * 9;
            const int dy = tap / 3, dx = tap - dy * 3;

            // exactly two commit groups per stage (real or empty)
            if (tap == 0 && kc + 1 < 8) fill_B(kc + 1); else CP_COMMIT();
            if (s + 1 < 72)             fill_A(s + 1);  else CP_COMMIT();

            CP_WAIT(2);                 // A(s) and B(kc) complete
            __syncthreads();

            const uint32_t sA  = sb + ((s & 1) << 14);
            const uint32_t sBb = sB0 + (uint32_t)(kc & 1) * 33792u;

            // halo row index for each 16-pixel B group (per lane)
            int hRow[2];
#pragma unroll
            for (int h = 0; h < 2; h++) {
                const int pix = n_base + (h << 4) + bRow;
                hRow[h] = ((pix >> 6) + dy) * 66 + (pix & 63) + dx;
            }

#pragma unroll
            for (int ks = 0; ks < 4; ks++) {
                const int kb = ks << 5;          // 32B per k16 step
                uint32_t ah[4][4], bh[2][4];
#pragma unroll
                for (int mt = 0; mt < 4; mt++)
                    ldsm4(ah[mt], sA + SWZ(((m_base + (mt << 4) + la15) << 7) + kb + aK));
#pragma unroll
                for (int h = 0; h < 2; h++)
                    ldsm4(bh[h], sBb + SWZ((hRow[h] << 7) + kb + bK));
#pragma unroll
                for (int mt = 0; mt < 4; mt++)
#pragma unroll
                    for (int nt = 0; nt < 4; nt++)
                        mma16816(acc[mt][nt], ah[mt], &bh[nt >> 1][(nt & 1) << 1]);
            }
            __syncthreads();            // protects buffer rotation
        }

        // epilogue: demod scale + float2 stores
        const int oc0  = ocb + m_base + (lane >> 2);
        const int pixb = n0 + n_base + ((lane & 3) << 1);
#pragma unroll
        for (int mt = 0; mt < 4; mt++) {
            const int ocr = oc0 + (mt << 4);
            const float dm0 = g_dm[b * 512 + ocr];
            const float dm1 = g_dm[b * 512 + ocr + 8];
            float* p0 = out + (((size_t)(b * 512 + ocr)) << 12);
            float* p1 = p0 + (8 << 12);
#pragma unroll
            for (int nt = 0; nt < 4; nt++) {
                const int px = pixb + (nt << 3);
                *(float2*)(p0 + px) = make_float2(acc[mt][nt][0] * dm0,
                                                  acc[mt][nt][1] * dm0);
                *(float2*)(p1 + px) = make_float2(acc[mt][nt][2] * dm1,
                                                  acc[mt][nt][3] * dm1);
            }
        }
    }
}

// ------------------------- launch ------------------------------------------
// Prep DAG (events fork/join, capture-safe; streams/events created once on
// the first non-captured call):
//   main:  style ──────────► xconv ───────────────► mma
//   side:  wprep ─► demod ─► xborder ──(e2)───────┘
extern "C" void kernel_launch(void* const* d_in, const int* in_sizes, int n_in,
                              void* d_out, int out_size) {
    const float* input  = (const float*)d_in[0];   // [8,512,64,64]
    const float* style  = (const float*)d_in[1];   // [8,512]
    const float* weight = (const float*)d_in[2];   // [1,512,512,3,3]
    const float* mod_w  = (const float*)d_in[3];   // [512,512]
    const float* mod_b  = (const float*)d_in[4];   // [512]
    float* out = (float*)d_out;                    // [8,512,64,64]

    static cudaStream_t s2 = nullptr;
    static cudaEvent_t e0 = nullptr, e1 = nullptr, e2 = nullptr;
    static bool cfg = false;
    if (!cfg) {
        cudaStreamCreateWithFlags(&s2, cudaStreamNonBlocking);
        cudaEventCreateWithFlags(&e0, cudaEventDisableTiming);
        cudaEventCreateWithFlags(&e1, cudaEventDisableTiming);
        cudaEventCreateWithFlags(&e2, cudaEventDisableTiming);
        cudaFuncSetAttribute(k_mma, cudaFuncAttributeMaxDynamicSharedMemorySize,
                             32768 + 2 * 33792 + 1024);
        cfg = true;
    }
    const int SMEM_DYN = 32768 + 2 * 33792 + 1024;

    // fork side stream off the (possibly capturing) main stream
    cudaEventRecord(e0, 0);
    cudaStreamWaitEvent(s2, e0, 0);

    k_wprep <<<1024, 256, 0, s2>>>(weight);        // independent
    k_style <<<512, 256>>>(style, mod_w, mod_b);   // main
    cudaEventRecord(e1, 0);                        // style done
    cudaStreamWaitEvent(s2, e1, 0);
    k_demod <<<512, 256, 0, s2>>>();               // needs style + wprep
    k_xborder<<<2080, 256, 0, s2>>>();             // disjoint g_xf region
    cudaEventRecord(e2, s2);

    k_xconv <<<dim3(64, 8, 8), dim3(32, 8)>>>(input);  // main, needs style

    cudaStreamWaitEvent(0, e2, 0);                 // join before mma
    k_mma   <<<896, 256, SMEM_DYN>>>(out);         // 128 doubles first
}